// round 10
// baseline (speedup 1.0000x reference)
#include <cuda_runtime.h>
#include <cstdint>

#define NN   8192
#define DIN  128
#define BM   32
#define KC   32
#define NCH  (NN / KC)
#define THREADS 256
#define GRID (NN / BM)

#define TSTR 36                            // T/a + A-tile row stride (floats)
#define ARR_FLOATS (BM * TSTR)             // 1152 floats per array
#define STG_FLOATS (5 * ARR_FLOATS)        // 5760 per stage (T0..T3, a)
#define ATILE_OFF (3 * STG_FLOATS)         // 17280
#define MAIN_FLOATS (ATILE_OFF + ARR_FLOATS)   // 18432 (73728 B)
#define HSTRIDE 132
#define WSTRIDE 130
#define EPI_FLOATS (BM * HSTRIDE + DIN * WSTRIDE)  // 20864 (83456 B)
#define SMEM_BYTES (EPI_FLOATS * 4)        // 83456  -> 2 CTAs/SM

typedef unsigned long long ull;

// ---------------- helpers ----------------
__device__ __forceinline__ uint32_t smem_u32(const void* p) {
    uint32_t r;
    asm("{ .reg .u64 t; cvta.to.shared.u64 t, %1; cvt.u32.u64 %0, t; }" : "=r"(r) : "l"(p));
    return r;
}
__device__ __forceinline__ void cpasync16(uint32_t dst, const void* src) {
    asm volatile("cp.async.cg.shared.global [%0], [%1], 16;" :: "r"(dst), "l"(src));
}
#define CP_COMMIT() asm volatile("cp.async.commit_group;" ::: "memory")
#define CP_WAIT(n)  asm volatile("cp.async.wait_group %0;" :: "n"(n) : "memory")

__device__ __forceinline__ uint32_t cvt_tf32(float v) {
    uint32_t r; asm("cvt.rna.tf32.f32 %0, %1;" : "=r"(r) : "f"(v)); return r;
}
__device__ __forceinline__ void mma_tf32(float* d, const uint32_t* a, uint32_t b0, uint32_t b1) {
    asm volatile(
        "mma.sync.aligned.m16n8k8.row.col.f32.tf32.tf32.f32 "
        "{%0,%1,%2,%3}, {%4,%5,%6,%7}, {%8,%9}, {%0,%1,%2,%3};"
        : "+f"(d[0]), "+f"(d[1]), "+f"(d[2]), "+f"(d[3])
        : "r"(a[0]), "r"(a[1]), "r"(a[2]), "r"(a[3]), "r"(b0), "r"(b1));
}
__device__ __forceinline__ void ffma2(ull& acc, ull q, ull x) {
    asm volatile("fma.rn.f32x2 %0, %1, %2, %0;" : "+l"(acc) : "l"(q), "l"(x));
}
__device__ __forceinline__ ull rep2(float v) {
    ull r; asm("mov.b64 %0, {%1, %1};" : "=l"(r) : "f"(v)); return r;
}
__device__ __forceinline__ ull pack2(float lo, float hi) {
    ull r; asm("mov.b64 %0, {%1, %2};" : "=l"(r) : "f"(lo), "f"(hi)); return r;
}
__device__ __forceinline__ float2 unp2(ull v) {
    float2 r; asm("mov.b64 {%0, %1}, %2;" : "=f"(r.x), "=f"(r.y) : "l"(v)); return r;
}

__global__ void __launch_bounds__(THREADS, 2)
ggd_kernel(const float* __restrict__ theta,
           const float* __restrict__ T,      // [4][8192][8192]
           const float* __restrict__ x,      // [8192][128]
           const float* __restrict__ a,      // [8192][8192]
           const float* __restrict__ alpha,  // [128]
           const float* __restrict__ W,      // [128][128]
           const float* __restrict__ bias,   // [128]
           float* __restrict__ out)          // [8192][128]
{
    extern __shared__ float smf[];
    const uint32_t sb = smem_u32(smf);
    const int tid  = threadIdx.x;
    const int lane = tid & 31;
    const int wid  = tid >> 5;          // 0..7: warp owns 16 output cols
    const int i0   = blockIdx.x * BM;

    const float th0 = theta[0], th1 = theta[1], th2 = theta[2], th3 = theta[3];

    // ---- cp.async staging map (T0..T3, a): one 16B granule per array ----
    const int gcol  = tid & 7;          // 16B granule within 128B row
    const int growb = tid >> 3;         // 0..31 row
    const size_t SLICE = (size_t)NN * NN;
    const float* gTA[5];
    #pragma unroll
    for (int k = 0; k < 4; ++k)
        gTA[k] = T + k * SLICE + (size_t)(i0 + growb) * NN + gcol * 4;
    gTA[4] = a + (size_t)(i0 + growb) * NN + gcol * 4;

    auto LOAD = [&](int ch, int s) {
        const int j0 = ch * KC;
        const uint32_t sbase = sb + (uint32_t)(s * STG_FLOATS) * 4u;
        #pragma unroll
        for (int arr = 0; arr < 5; ++arr) {
            const uint32_t dst = sbase +
                (uint32_t)(arr * ARR_FLOATS + growb * TSTR + gcol * 4) * 4u;
            cpasync16(dst, gTA[arr] + j0);
        }
        CP_COMMIT();
    };

    // ---- B fragments direct from global x (L2-hot), register prefetch ----
    // b[ks*4 + nt*2 + half] = x[j0 + 8ks + (lane&3) + 4half][16*wid + 8nt + (lane>>2)]
    const float* px = x + (size_t)(lane & 3) * DIN + 16 * wid + (lane >> 2);
    auto LOADB = [&](int ch, float* b) {
        const int j0 = ch * KC;
        #pragma unroll
        for (int ks = 0; ks < 4; ++ks)
            #pragma unroll
            for (int nt = 0; nt < 2; ++nt)
                #pragma unroll
                for (int half = 0; half < 2; ++half)
                    b[ks * 4 + nt * 2 + half] =
                        __ldg(px + (size_t)(j0 + 8 * ks + 4 * half) * DIN + 8 * nt);
    };

    // ---- q build: each thread one float4 of the 32x32 tile ----
    const int qrow = tid & 31;
    const int qc4  = tid >> 5;          // 0..7
    auto QBUILD = [&](int s) {
        const float* st = smf + s * STG_FLOATS;
        float* at = smf + ATILE_OFF;
        const int jf = qc4 * 4;
        const float4 t0 = *(const float4*)(st + 0 * ARR_FLOATS + qrow * TSTR + jf);
        const float4 t1 = *(const float4*)(st + 1 * ARR_FLOATS + qrow * TSTR + jf);
        const float4 t2 = *(const float4*)(st + 2 * ARR_FLOATS + qrow * TSTR + jf);
        const float4 t3 = *(const float4*)(st + 3 * ARR_FLOATS + qrow * TSTR + jf);
        const float4 av = *(const float4*)(st + 4 * ARR_FLOATS + qrow * TSTR + jf);
        uint4 q;
        q.x = cvt_tf32(av.x * (th0 * t0.x + th1 * t1.x + th2 * t2.x + th3 * t3.x));
        q.y = cvt_tf32(av.y * (th0 * t0.y + th1 * t1.y + th2 * t2.y + th3 * t3.y));
        q.z = cvt_tf32(av.z * (th0 * t0.z + th1 * t1.z + th2 * t2.z + th3 * t3.z));
        q.w = cvt_tf32(av.w * (th0 * t0.w + th1 * t1.w + th2 * t2.w + th3 * t3.w));
        *(uint4*)(void*)(at + qrow * TSTR + jf) = q;
    };

    const int abase = (lane >> 2) * TSTR + (lane & 3);

    float acc[2][2][4];                  // [mt][nt][frag]
    #pragma unroll
    for (int mt = 0; mt < 2; ++mt)
        #pragma unroll
        for (int nt = 0; nt < 2; ++nt)
            #pragma unroll
            for (int c = 0; c < 4; ++c) acc[mt][nt][c] = 0.0f;

    float bcur[16], bnx[16];
    LOAD(0, 0);
    LOAD(1, 1);
    LOADB(0, bcur);

    for (int ch = 0; ch < NCH; ++ch) {
        const int s = ch % 3;
        if (ch + 1 < NCH) CP_WAIT(1); else CP_WAIT(0);
        __syncthreads();                       // stage s visible; prev MMA done by all
        if (ch + 2 < NCH) LOAD(ch + 2, (ch + 2) % 3);
        LOADB(ch + 1 < NCH ? ch + 1 : ch, bnx);   // LDGs in flight through this chunk
        QBUILD(s);
        __syncthreads();                       // A-tile ready
        {
            const uint32_t* At = (const uint32_t*)(smf + ATILE_OFF);
            #pragma unroll
            for (int ks = 0; ks < 4; ++ks) {
                uint32_t af[2][4];
                #pragma unroll
                for (int mt = 0; mt < 2; ++mt) {
                    const int ab = abase + mt * 16 * TSTR + 8 * ks;
                    af[mt][0] = At[ab];
                    af[mt][1] = At[ab + 8 * TSTR];
                    af[mt][2] = At[ab + 4];
                    af[mt][3] = At[ab + 8 * TSTR + 4];
                }
                #pragma unroll
                for (int nt = 0; nt < 2; ++nt) {
                    const uint32_t b0 = cvt_tf32(bcur[ks * 4 + nt * 2 + 0]);
                    const uint32_t b1 = cvt_tf32(bcur[ks * 4 + nt * 2 + 1]);
                    mma_tf32(acc[0][nt], af[0], b0, b1);
                    mma_tf32(acc[1][nt], af[1], b0, b1);
                }
            }
        }
        #pragma unroll
        for (int i = 0; i < 16; ++i) bcur[i] = bnx[i];
    }
    __syncthreads();                           // all MMA/LDS done before smem reuse

    // ---------------- epilogue: PReLU -> hs, then @ W^T + b (fp32) ----------------
    float* hs = smf;                     // [BM][HSTRIDE]
    float* wt = smf + BM * HSTRIDE;      // [DIN][WSTRIDE]

    {
        const int r0 = lane >> 2;
        #pragma unroll
        for (int mt = 0; mt < 2; ++mt)
            #pragma unroll
            for (int nt = 0; nt < 2; ++nt) {
                const int col = 16 * wid + 8 * nt + 2 * (lane & 3);
                const float a0 = __ldg(alpha + col), a1 = __ldg(alpha + col + 1);
                float2 h0, h1;
                h0.x = acc[mt][nt][0] > 0.0f ? acc[mt][nt][0] : a0 * acc[mt][nt][0];
                h0.y = acc[mt][nt][1] > 0.0f ? acc[mt][nt][1] : a1 * acc[mt][nt][1];
                h1.x = acc[mt][nt][2] > 0.0f ? acc[mt][nt][2] : a0 * acc[mt][nt][2];
                h1.y = acc[mt][nt][3] > 0.0f ? acc[mt][nt][3] : a1 * acc[mt][nt][3];
                *(float2*)(hs + (16 * mt + r0) * HSTRIDE + col)     = h0;
                *(float2*)(hs + (16 * mt + r0 + 8) * HSTRIDE + col) = h1;
            }
    }
    for (int idx = tid; idx < DIN * DIN; idx += THREADS) {
        const int din = idx >> 7, dof = idx & 127;
        wt[din * WSTRIDE + dof] = __ldg(W + dof * DIN + din);
    }
    __syncthreads();

    const int ti = tid >> 4;             // 0..15 -> 2 rows each
    const int td = tid & 15;
    ull oacc[2][4];
    #pragma unroll
    for (int c2 = 0; c2 < 4; ++c2) {
        const int d0 = 2 * (td + 16 * c2);
        const float2 bb = *(const float2*)(bias + d0);
        const ull bv = pack2(bb.x, bb.y);
        #pragma unroll
        for (int r = 0; r < 2; ++r) oacc[r][c2] = bv;
    }
    #pragma unroll 4
    for (int din = 0; din < DIN; ++din) {
        ull wv[4];
        #pragma unroll
        for (int c2 = 0; c2 < 4; ++c2)
            wv[c2] = *(const ull*)(wt + din * WSTRIDE + 2 * (td + 16 * c2));
        #pragma unroll
        for (int r = 0; r < 2; ++r) {
            const ull h2 = rep2(hs[(ti * 2 + r) * HSTRIDE + din]);
            #pragma unroll
            for (int c2 = 0; c2 < 4; ++c2) ffma2(oacc[r][c2], h2, wv[c2]);
        }
    }
    #pragma unroll
    for (int r = 0; r < 2; ++r) {
        float* orow = out + (size_t)(i0 + ti * 2 + r) * DIN;
        #pragma unroll
        for (int c2 = 0; c2 < 4; ++c2) {
            const float2 o = unp2(oacc[r][c2]);
            *(float2*)(orow + 2 * (td + 16 * c2)) = o;
        }
    }
}

extern "C" void kernel_launch(void* const* d_in, const int* in_sizes, int n_in,
                              void* d_out, int out_size) {
    const float* theta = (const float*)d_in[0];
    const float* T     = (const float*)d_in[1];
    const float* x     = (const float*)d_in[2];
    const float* a     = (const float*)d_in[3];
    const float* alpha = (const float*)d_in[4];
    const float* W     = (const float*)d_in[5];
    const float* b     = (const float*)d_in[6];
    float* out = (float*)d_out;

    cudaFuncSetAttribute(ggd_kernel, cudaFuncAttributeMaxDynamicSharedMemorySize, SMEM_BYTES);
    ggd_kernel<<<GRID, THREADS, SMEM_BYTES>>>(theta, T, x, a, alpha, W, b, out);
}

// round 11
// speedup vs baseline: 1.4861x; 1.4861x over previous
#include <cuda_runtime.h>
#include <cstdint>

#define NN   8192
#define DIN  128
#define BM   64
#define KC   32
#define NCH  (NN / KC)
#define THREADS 512
#define GRID (NN / BM)

#define TSTR 36                              // T/a + A-tile row stride (floats)
#define XSTR 136                             // x tile row stride (floats)
#define ARR_FLOATS (BM * TSTR)               // 2304
#define TA_STAGE (5 * ARR_FLOATS)            // 11520 (T0..T3, a)
#define X_OFF    (3 * TA_STAGE)              // 34560 (3 T/a slots)
#define XTILE    (KC * XSTR)                 // 4352
#define AT_OFF   (X_OFF + 4 * XTILE)         // 51968 (4 x slots)
#define SMEM_FLOATS (AT_OFF + 2 * ARR_FLOATS)   // 56576
#define SMEM_BYTES (SMEM_FLOATS * 4)         // 226304

#define HSTRIDE 132
#define WSTRIDE 130

typedef unsigned long long ull;

// ---------------- helpers ----------------
__device__ __forceinline__ uint32_t smem_u32(const void* p) {
    uint32_t r;
    asm("{ .reg .u64 t; cvta.to.shared.u64 t, %1; cvt.u32.u64 %0, t; }" : "=r"(r) : "l"(p));
    return r;
}
__device__ __forceinline__ void cpasync16(uint32_t dst, const void* src) {
    asm volatile("cp.async.cg.shared.global [%0], [%1], 16;" :: "r"(dst), "l"(src));
}
#define CP_COMMIT() asm volatile("cp.async.commit_group;" ::: "memory")
#define CP_WAIT(n)  asm volatile("cp.async.wait_group %0;" :: "n"(n) : "memory")

__device__ __forceinline__ uint32_t cvt_tf32(float v) {
    uint32_t r; asm("cvt.rna.tf32.f32 %0, %1;" : "=r"(r) : "f"(v)); return r;
}
__device__ __forceinline__ void mma_tf32(float* d, const uint32_t* a, uint32_t b0, uint32_t b1) {
    asm volatile(
        "mma.sync.aligned.m16n8k8.row.col.f32.tf32.tf32.f32 "
        "{%0,%1,%2,%3}, {%4,%5,%6,%7}, {%8,%9}, {%0,%1,%2,%3};"
        : "+f"(d[0]), "+f"(d[1]), "+f"(d[2]), "+f"(d[3])
        : "r"(a[0]), "r"(a[1]), "r"(a[2]), "r"(a[3]), "r"(b0), "r"(b1));
}
__device__ __forceinline__ void ffma2(ull& acc, ull q, ull x) {
    asm volatile("fma.rn.f32x2 %0, %1, %2, %0;" : "+l"(acc) : "l"(q), "l"(x));
}
__device__ __forceinline__ ull rep2(float v) {
    ull r; asm("mov.b64 %0, {%1, %1};" : "=l"(r) : "f"(v)); return r;
}
__device__ __forceinline__ ull pack2(float lo, float hi) {
    ull r; asm("mov.b64 %0, {%1, %2};" : "=l"(r) : "f"(lo), "f"(hi)); return r;
}
__device__ __forceinline__ float2 unp2(ull v) {
    float2 r; asm("mov.b64 {%0, %1}, %2;" : "=f"(r.x), "=f"(r.y) : "l"(v)); return r;
}

__global__ void __launch_bounds__(THREADS, 1)
ggd_kernel(const float* __restrict__ theta,
           const float* __restrict__ T,      // [4][8192][8192]
           const float* __restrict__ x,      // [8192][128]
           const float* __restrict__ a,      // [8192][8192]
           const float* __restrict__ alpha,  // [128]
           const float* __restrict__ W,      // [128][128]
           const float* __restrict__ bias,   // [128]
           float* __restrict__ out)          // [8192][128]
{
    extern __shared__ float smf[];
    const uint32_t sb = smem_u32(smf);
    const int tid  = threadIdx.x;
    const int lane = tid & 31;
    const int wid  = tid >> 5;          // 0..15
    const int wm   = wid & 3;           // 16-row m-tile
    const int wn   = wid >> 2;          // 32-col n-group
    const int i0   = blockIdx.x * BM;

    const float th0 = theta[0], th1 = theta[1], th2 = theta[2], th3 = theta[3];

    // ---- cp.async staging maps ----
    const int gcol = tid & 7;           // 16B granule within 128B row
    const int grow = tid >> 3;          // 0..63
    const size_t SLICE = (size_t)NN * NN;
    const float* gTA[5];
    #pragma unroll
    for (int k = 0; k < 4; ++k)
        gTA[k] = T + k * SLICE + (size_t)(i0 + grow) * NN + gcol * 4;
    gTA[4] = a + (size_t)(i0 + grow) * NN + gcol * 4;
    const int xcol = tid & 31;          // 16B granule within 512B x row
    const int xrow = tid >> 5;          // 0..15 (+16 for rr=1)
    const float* gx = x + (size_t)xrow * DIN + xcol * 4;

    auto LOAD = [&](int ch) {
        const int j0 = ch * KC;
        const uint32_t tabase = sb + (uint32_t)((ch % 3) * TA_STAGE) * 4u;
        #pragma unroll
        for (int arr = 0; arr < 5; ++arr) {
            const uint32_t dst = tabase +
                (uint32_t)(arr * ARR_FLOATS + grow * TSTR + gcol * 4) * 4u;
            cpasync16(dst, gTA[arr] + j0);
        }
        const uint32_t xbase = sb + (uint32_t)(X_OFF + (ch & 3) * XTILE) * 4u;
        #pragma unroll
        for (int rr = 0; rr < 2; ++rr) {
            const uint32_t dst = xbase +
                (uint32_t)((xrow + 16 * rr) * XSTR + xcol * 4) * 4u;
            cpasync16(dst, gx + (size_t)(j0 + 16 * rr) * DIN);
        }
        CP_COMMIT();
    };

    // ---- q build: one float4 per thread (64 rows x 8 float4-cols = 512) ----
    const int qrow = tid & 63;
    const int qc4  = tid >> 6;          // 0..7
    auto QBUILD = [&](int ch) {
        const float* st = smf + (ch % 3) * TA_STAGE;
        float* at = smf + AT_OFF + (ch & 1) * ARR_FLOATS;
        const int jf = qc4 * 4;
        const float4 t0 = *(const float4*)(st + 0 * ARR_FLOATS + qrow * TSTR + jf);
        const float4 t1 = *(const float4*)(st + 1 * ARR_FLOATS + qrow * TSTR + jf);
        const float4 t2 = *(const float4*)(st + 2 * ARR_FLOATS + qrow * TSTR + jf);
        const float4 t3 = *(const float4*)(st + 3 * ARR_FLOATS + qrow * TSTR + jf);
        const float4 av = *(const float4*)(st + 4 * ARR_FLOATS + qrow * TSTR + jf);
        uint4 q;
        q.x = cvt_tf32(av.x * (th0 * t0.x + th1 * t1.x + th2 * t2.x + th3 * t3.x));
        q.y = cvt_tf32(av.y * (th0 * t0.y + th1 * t1.y + th2 * t2.y + th3 * t3.y));
        q.z = cvt_tf32(av.z * (th0 * t0.z + th1 * t1.z + th2 * t2.z + th3 * t3.z));
        q.w = cvt_tf32(av.w * (th0 * t0.w + th1 * t1.w + th2 * t2.w + th3 * t3.w));
        *(uint4*)(void*)(at + qrow * TSTR + jf) = q;
    };

    // ---- MMA fragment bases ----
    const int abase = (16 * wm + (lane >> 2)) * TSTR + (lane & 3);
    const int bbase = (lane & 3) * XSTR + 32 * wn + (lane >> 2);

    float acc[4][4];
    #pragma unroll
    for (int nt = 0; nt < 4; ++nt)
        #pragma unroll
        for (int c = 0; c < 4; ++c) acc[nt][c] = 0.0f;

    // prologue
    LOAD(0);
    LOAD(1);
    CP_WAIT(1);
    __syncthreads();
    QBUILD(0);

    for (int ch = 0; ch < NCH; ++ch) {
        if (ch + 2 < NCH) { LOAD(ch + 2); CP_WAIT(1); }
        else              { CP_WAIT(0); }
        __syncthreads();    // A-tile(ch) + stage(ch+1) visible to all; prior readers done
        if (ch + 1 < NCH) QBUILD(ch + 1);           // overlaps MMA(ch), disjoint smem
        {
            const uint32_t* At = (const uint32_t*)(smf + AT_OFF + (ch & 1) * ARR_FLOATS);
            const uint32_t* Bs = (const uint32_t*)(smf + X_OFF + (ch & 3) * XTILE);
            #pragma unroll
            for (int ks = 0; ks < 4; ++ks) {
                uint32_t af[4];
                const int ab = abase + 8 * ks;
                af[0] = At[ab];
                af[1] = At[ab + 8 * TSTR];
                af[2] = At[ab + 4];
                af[3] = At[ab + 8 * TSTR + 4];
                #pragma unroll
                for (int nt = 0; nt < 4; ++nt) {
                    const int bb = bbase + 8 * ks * XSTR + 8 * nt;
                    mma_tf32(acc[nt], af, Bs[bb], Bs[bb + 4 * XSTR]);
                }
            }
        }
    }
    __syncthreads();        // all MMA/LDS done before smem reuse

    // ---------------- epilogue: PReLU -> hs, then @ W^T + b (fp32) ----------------
    float* hs = smf;                     // [BM][HSTRIDE]
    float* wt = smf + BM * HSTRIDE;      // [DIN][WSTRIDE]

    {
        const int r0 = 16 * wm + (lane >> 2);
        #pragma unroll
        for (int nt = 0; nt < 4; ++nt) {
            const int col = 32 * wn + 8 * nt + 2 * (lane & 3);
            const float a0 = __ldg(alpha + col), a1 = __ldg(alpha + col + 1);
            float2 h0, h1;
            h0.x = acc[nt][0] > 0.0f ? acc[nt][0] : a0 * acc[nt][0];
            h0.y = acc[nt][1] > 0.0f ? acc[nt][1] : a1 * acc[nt][1];
            h1.x = acc[nt][2] > 0.0f ? acc[nt][2] : a0 * acc[nt][2];
            h1.y = acc[nt][3] > 0.0f ? acc[nt][3] : a1 * acc[nt][3];
            *(float2*)(hs + r0 * HSTRIDE + col)       = h0;
            *(float2*)(hs + (r0 + 8) * HSTRIDE + col) = h1;
        }
    }
    for (int idx = tid; idx < DIN * DIN; idx += THREADS) {
        const int din = idx >> 7, dof = idx & 127;
        wt[din * WSTRIDE + dof] = __ldg(W + dof * DIN + din);
    }
    __syncthreads();

    const int ti = tid >> 4;             // 0..31 -> 2 rows each
    const int td = tid & 15;
    ull oacc[2][4];
    #pragma unroll
    for (int c2 = 0; c2 < 4; ++c2) {
        const int d0 = 2 * (td + 16 * c2);
        const float2 bb = *(const float2*)(bias + d0);
        const ull bv = pack2(bb.x, bb.y);
        #pragma unroll
        for (int r = 0; r < 2; ++r) oacc[r][c2] = bv;
    }
    #pragma unroll 4
    for (int din = 0; din < DIN; ++din) {
        ull wv[4];
        #pragma unroll
        for (int c2 = 0; c2 < 4; ++c2)
            wv[c2] = *(const ull*)(wt + din * WSTRIDE + 2 * (td + 16 * c2));
        #pragma unroll
        for (int r = 0; r < 2; ++r) {
            const ull h2 = rep2(hs[(ti * 2 + r) * HSTRIDE + din]);
            #pragma unroll
            for (int c2 = 0; c2 < 4; ++c2) ffma2(oacc[r][c2], h2, wv[c2]);
        }
    }
    #pragma unroll
    for (int r = 0; r < 2; ++r) {
        float* orow = out + (size_t)(i0 + ti * 2 + r) * DIN;
        #pragma unroll
        for (int c2 = 0; c2 < 4; ++c2) {
            const float2 o = unp2(oacc[r][c2]);
            *(float2*)(orow + 2 * (td + 16 * c2)) = o;
        }
    }
}

extern "C" void kernel_launch(void* const* d_in, const int* in_sizes, int n_in,
                              void* d_out, int out_size) {
    const float* theta = (const float*)d_in[0];
    const float* T     = (const float*)d_in[1];
    const float* x     = (const float*)d_in[2];
    const float* a     = (const float*)d_in[3];
    const float* alpha = (const float*)d_in[4];
    const float* W     = (const float*)d_in[5];
    const float* b     = (const float*)d_in[6];
    float* out = (float*)d_out;

    cudaFuncSetAttribute(ggd_kernel, cudaFuncAttributeMaxDynamicSharedMemorySize, SMEM_BYTES);
    ggd_kernel<<<GRID, THREADS, SMEM_BYTES>>>(theta, T, x, a, alpha, W, b, out);
}

// round 15
// speedup vs baseline: 1.6106x; 1.0838x over previous
#include <cuda_runtime.h>
#include <cstdint>

#define NN   8192
#define DIN  128
#define BM   64
#define KC   32
#define NCH  (NN / KC)
#define THREADS 512
#define GRID (NN / BM)

#define TSTR 36                              // A-tile row stride (floats)
#define XSTR 136                             // x tile row stride (floats)
#define ARR_FLOATS (BM * TSTR)               // 2304 (A-tile)
#define XTILE (KC * XSTR)                    // 4352
#define AT_OFF (4 * XTILE)                   // 17408 (4 x slots first)
#define MAIN_FLOATS (AT_OFF + 2 * ARR_FLOATS)   // 22016 (88064 B)

#define HSTRIDE 132
#define WSTRIDE 130
#define EPI_FLOATS (BM * HSTRIDE + DIN * WSTRIDE)   // 25088 (100352 B)

// smem must cover BOTH phases (epilogue reuses the buffer)
#define SMEM_FLOATS (MAIN_FLOATS > EPI_FLOATS ? MAIN_FLOATS : EPI_FLOATS)
#define SMEM_BYTES (SMEM_FLOATS * 4)         // 100352

typedef unsigned long long ull;

// ---------------- helpers ----------------
__device__ __forceinline__ uint32_t smem_u32(const void* p) {
    uint32_t r;
    asm("{ .reg .u64 t; cvta.to.shared.u64 t, %1; cvt.u32.u64 %0, t; }" : "=r"(r) : "l"(p));
    return r;
}
__device__ __forceinline__ void cpasync16(uint32_t dst, const void* src) {
    asm volatile("cp.async.cg.shared.global [%0], [%1], 16;" :: "r"(dst), "l"(src));
}
#define CP_COMMIT() asm volatile("cp.async.commit_group;" ::: "memory")
#define CP_WAIT(n)  asm volatile("cp.async.wait_group %0;" :: "n"(n) : "memory")

__device__ __forceinline__ uint32_t cvt_tf32(float v) {
    uint32_t r; asm("cvt.rna.tf32.f32 %0, %1;" : "=r"(r) : "f"(v)); return r;
}
__device__ __forceinline__ void mma_tf32(float* d, const uint32_t* a, uint32_t b0, uint32_t b1) {
    asm volatile(
        "mma.sync.aligned.m16n8k8.row.col.f32.tf32.tf32.f32 "
        "{%0,%1,%2,%3}, {%4,%5,%6,%7}, {%8,%9}, {%0,%1,%2,%3};"
        : "+f"(d[0]), "+f"(d[1]), "+f"(d[2]), "+f"(d[3])
        : "r"(a[0]), "r"(a[1]), "r"(a[2]), "r"(a[3]), "r"(b0), "r"(b1));
}
__device__ __forceinline__ void ffma2(ull& acc, ull q, ull x) {
    asm volatile("fma.rn.f32x2 %0, %1, %2, %0;" : "+l"(acc) : "l"(q), "l"(x));
}
__device__ __forceinline__ ull rep2(float v) {
    ull r; asm("mov.b64 %0, {%1, %1};" : "=l"(r) : "f"(v)); return r;
}
__device__ __forceinline__ ull pack2(float lo, float hi) {
    ull r; asm("mov.b64 %0, {%1, %2};" : "=l"(r) : "f"(lo), "f"(hi)); return r;
}
__device__ __forceinline__ float2 unp2(ull v) {
    float2 r; asm("mov.b64 {%0, %1}, %2;" : "=f"(r.x), "=f"(r.y) : "l"(v)); return r;
}

__global__ void __launch_bounds__(THREADS, 1)
ggd_kernel(const float* __restrict__ theta,
           const float* __restrict__ T,      // [4][8192][8192]
           const float* __restrict__ x,      // [8192][128]
           const float* __restrict__ a,      // [8192][8192]
           const float* __restrict__ alpha,  // [128]
           const float* __restrict__ W,      // [128][128]
           const float* __restrict__ bias,   // [128]
           float* __restrict__ out)          // [8192][128]
{
    extern __shared__ float smf[];
    const uint32_t sb = smem_u32(smf);
    const int tid  = threadIdx.x;
    const int lane = tid & 31;
    const int wid  = tid >> 5;          // 0..15
    const int wm   = wid & 3;           // 16-row m-tile
    const int wn   = wid >> 2;          // 32-col n-group
    const int i0   = blockIdx.x * BM;

    const float th0 = theta[0], th1 = theta[1], th2 = theta[2], th3 = theta[3];

    // ---- T/a register-path load: warp w owns rows 4w..4w+3, lane = column ----
    const size_t SLICE = (size_t)NN * NN;
    const float* pTA[5];
    #pragma unroll
    for (int k = 0; k < 4; ++k)
        pTA[k] = T + k * SLICE + (size_t)(i0 + 4 * wid) * NN + lane;
    pTA[4] = a + (size_t)(i0 + 4 * wid) * NN + lane;

    float buf[20];                       // [arr][row] prefetch buffer
    auto LDGT = [&](int ch) {
        const int j0 = ch * KC;
        #pragma unroll
        for (int arr = 0; arr < 5; ++arr)
            #pragma unroll
            for (int r = 0; r < 4; ++r)
                buf[arr * 4 + r] = __ldcs(pTA[arr] + (size_t)r * NN + j0);
    };

    // q-build from registers -> A-tile (8KB STS, conflict-free)
    auto QBUILD = [&](int ch) {
        float* at = smf + AT_OFF + (ch & 1) * ARR_FLOATS;
        #pragma unroll
        for (int r = 0; r < 4; ++r) {
            const float q = buf[16 + r] *
                (th0 * buf[r] + th1 * buf[4 + r] + th2 * buf[8 + r] + th3 * buf[12 + r]);
            uint32_t qi = cvt_tf32(q);
            *(uint32_t*)(void*)(at + (4 * wid + r) * TSTR + lane) = qi;
        }
    };

    // ---- x staging via cp.async ----
    const int xcol = tid & 31;          // 16B granule within 512B x row
    const int xrow = tid >> 5;          // 0..15 (+16 for rr=1)
    const float* gx = x + (size_t)xrow * DIN + xcol * 4;
    auto LOADX = [&](int ch) {
        const int j0 = ch * KC;
        const uint32_t xbase = sb + (uint32_t)((ch & 3) * XTILE) * 4u;
        #pragma unroll
        for (int rr = 0; rr < 2; ++rr) {
            const uint32_t dst = xbase +
                (uint32_t)((xrow + 16 * rr) * XSTR + xcol * 4) * 4u;
            cpasync16(dst, gx + (size_t)(j0 + 16 * rr) * DIN);
        }
        CP_COMMIT();
    };

    // ---- MMA fragment bases ----
    const int abase = (16 * wm + (lane >> 2)) * TSTR + (lane & 3);
    const int bbase = (lane & 3) * XSTR + 32 * wn + (lane >> 2);

    float acc[4][4];
    #pragma unroll
    for (int nt = 0; nt < 4; ++nt)
        #pragma unroll
        for (int c = 0; c < 4; ++c) acc[nt][c] = 0.0f;

    // prologue
    LOADX(0);
    LOADX(1);
    LDGT(0);
    QBUILD(0);                 // one-time exposed LDG latency
    LDGT(1);

    for (int ch = 0; ch < NCH; ++ch) {
        if (ch + 2 < NCH) { LOADX(ch + 2); CP_WAIT(1); }
        else              { CP_WAIT(0); }
        __syncthreads();       // A-tile(ch) + x(ch) visible; prior slot readers done
        {
            const uint32_t* At = (const uint32_t*)(smf + AT_OFF + (ch & 1) * ARR_FLOATS);
            const uint32_t* Bs = (const uint32_t*)(smf + (ch & 3) * XTILE);
            #pragma unroll
            for (int ks = 0; ks < 4; ++ks) {
                uint32_t af[4];
                const int ab = abase + 8 * ks;
                af[0] = At[ab];
                af[1] = At[ab + 8 * TSTR];
                af[2] = At[ab + 4];
                af[3] = At[ab + 8 * TSTR + 4];
                #pragma unroll
                for (int nt = 0; nt < 4; ++nt) {
                    const int bb = bbase + 8 * ks * XSTR + 8 * nt;
                    mma_tf32(acc[nt], af, Bs[bb], Bs[bb + 4 * XSTR]);
                }
            }
        }
        if (ch + 1 < NCH) QBUILD(ch + 1);    // consumes buf, writes other A-buf
        if (ch + 2 < NCH) LDGT(ch + 2);      // refill regs; ~1 chunk of latency cover
    }
    __syncthreads();           // all MMA/LDS done before smem reuse

    // ---------------- epilogue: PReLU -> hs, then @ W^T + b (fp32) ----------------
    float* hs = smf;                     // [BM][HSTRIDE]    8448 floats
    float* wt = smf + BM * HSTRIDE;      // [DIN][WSTRIDE]  16640 floats (fits: 25088 total)

    {
        const int r0 = 16 * wm + (lane >> 2);
        #pragma unroll
        for (int nt = 0; nt < 4; ++nt) {
            const int col = 32 * wn + 8 * nt + 2 * (lane & 3);
            const float a0 = __ldg(alpha + col), a1 = __ldg(alpha + col + 1);
            float2 h0, h1;
            h0.x = acc[nt][0] > 0.0f ? acc[nt][0] : a0 * acc[nt][0];
            h0.y = acc[nt][1] > 0.0f ? acc[nt][1] : a1 * acc[nt][1];
            h1.x = acc[nt][2] > 0.0f ? acc[nt][2] : a0 * acc[nt][2];
            h1.y = acc[nt][3] > 0.0f ? acc[nt][3] : a1 * acc[nt][3];
            *(float2*)(hs + r0 * HSTRIDE + col)       = h0;
            *(float2*)(hs + (r0 + 8) * HSTRIDE + col) = h1;
        }
    }
    for (int idx = tid; idx < DIN * DIN; idx += THREADS) {
        const int din = idx >> 7, dof = idx & 127;
        wt[din * WSTRIDE + dof] = __ldg(W + dof * DIN + din);
    }
    __syncthreads();

    const int ti = tid >> 4;             // 0..31 -> 2 rows each
    const int td = tid & 15;
    ull oacc[2][4];
    #pragma unroll
    for (int c2 = 0; c2 < 4; ++c2) {
        const int d0 = 2 * (td + 16 * c2);
        const float2 bb = *(const float2*)(bias + d0);
        const ull bv = pack2(bb.x, bb.y);
        #pragma unroll
        for (int r = 0; r < 2; ++r) oacc[r][c2] = bv;
    }
    #pragma unroll 4
    for (int din = 0; din < DIN; ++din) {
        ull wv[4];
        #pragma unroll
        for (int c2 = 0; c2 < 4; ++c2)
            wv[c2] = *(const ull*)(wt + din * WSTRIDE + 2 * (td + 16 * c2));
        #pragma unroll
        for (int r = 0; r < 2; ++r) {
            const ull h2 = rep2(hs[(ti * 2 + r) * HSTRIDE + din]);
            #pragma unroll
            for (int c2 = 0; c2 < 4; ++c2) ffma2(oacc[r][c2], h2, wv[c2]);
        }
    }
    #pragma unroll
    for (int r = 0; r < 2; ++r) {
        float* orow = out + (size_t)(i0 + ti * 2 + r) * DIN;
        #pragma unroll
        for (int c2 = 0; c2 < 4; ++c2) {
            const float2 o = unp2(oacc[r][c2]);
            *(float2*)(orow + 2 * (td + 16 * c2)) = o;
        }
    }
}

extern "C" void kernel_launch(void* const* d_in, const int* in_sizes, int n_in,
                              void* d_out, int out_size) {
    const float* theta = (const float*)d_in[0];
    const float* T     = (const float*)d_in[1];
    const float* x     = (const float*)d_in[2];
    const float* a     = (const float*)d_in[3];
    const float* alpha = (const float*)d_in[4];
    const float* W     = (const float*)d_in[5];
    const float* b     = (const float*)d_in[6];
    float* out = (float*)d_out;

    cudaFuncSetAttribute(ggd_kernel, cudaFuncAttributeMaxDynamicSharedMemorySize, SMEM_BYTES);
    ggd_kernel<<<GRID, THREADS, SMEM_BYTES>>>(theta, T, x, a, alpha, W, b, out);
}